// round 3
// baseline (speedup 1.0000x reference)
#include <cuda_runtime.h>
#include <math.h>

#define NP 36864          // 192*192 output pixels
#define WOUT 192
#define HIN 96

// ---------------- static scratch (no allocations allowed) ----------------
__device__ float g_a[64 * NP];          // stage-1 activations (both chains, sequential)
__device__ float g_b[256 * NP];         // stage-2 activations
__device__ float g_dw[576 * NP];        // dw logits (C=64, K*K=9)
__device__ float g_pw[192 * NP];        // pw weights (C=64, OC=3)
__device__ float g_mean[2 * 64 * NP];   // softmax(dw)-weighted mean
__device__ float g_s1[2 * 64 * NP];
__device__ float g_s2[2 * 64 * NP];
__device__ float g_sigma[2 * 2 * NP];
__device__ float g_xa[2 * 64 * NP];

// Buffer selectors resolved in DEVICE code — kernel_launch makes no runtime
// API calls other than kernel launches (graph-capture safe by construction).
#define BUF_A     0
#define BUF_B     1
#define BUF_DW    2
#define BUF_PW    3
#define BUF_MEAN  4
#define BUF_S1    5
#define BUF_S2    6
#define BUF_SIGMA 7
#define BUF_XA    8

__device__ __forceinline__ float* buf_ptr(int sel) {
    switch (sel) {
        case BUF_A:     return g_a;
        case BUF_B:     return g_b;
        case BUF_DW:    return g_dw;
        case BUF_PW:    return g_pw;
        case BUF_MEAN:  return g_mean;
        case BUF_S1:    return g_s1;
        case BUF_S2:    return g_s2;
        case BUF_SIGMA: return g_sigma;
        default:        return g_xa;
    }
}

// ---------------- 1x1 conv as GEMM ----------------
// Y[oc, p] = act(bias[oc] + sum_ic W[oc*IC+ic] * X[ic*NP + p])
// 64x64 tile, BK=16, 256 threads, 4x4 per-thread microtile.
// SRC == -1 means X comes from the kernel argument (external input).
template<int SRC, int DST, bool RELU>
__global__ void k_gemm1x1(const float* __restrict__ W, const float* __restrict__ bias,
                          const float* __restrict__ Xext, int IC) {
    const float* __restrict__ X = (SRC < 0) ? Xext : buf_ptr(SRC);
    float* __restrict__ Y = buf_ptr(DST);

    __shared__ float As[16][65];   // [k][m], padded against bank conflicts
    __shared__ float Bs[16][64];   // [k][n]
    const int tid = threadIdx.x;
    const int tx = tid & 15, ty = tid >> 4;
    const int m0 = blockIdx.y * 64;
    const int n0 = blockIdx.x * 64;

    float acc[4][4];
#pragma unroll
    for (int i = 0; i < 4; i++)
#pragma unroll
        for (int j = 0; j < 4; j++) acc[i][j] = 0.f;

    for (int k0 = 0; k0 < IC; k0 += 16) {
        // load W tile: k-contiguous in global for coalescing
#pragma unroll
        for (int i = 0; i < 4; i++) {
            int e = tid + i * 256;          // 0..1023
            int k = e & 15, m = e >> 4;
            As[k][m] = (k0 + k < IC) ? W[(m0 + m) * IC + k0 + k] : 0.f;
        }
        // load X tile: n-contiguous
#pragma unroll
        for (int i = 0; i < 4; i++) {
            int e = tid + i * 256;
            int n = e & 63, k = e >> 6;
            Bs[k][n] = (k0 + k < IC) ? X[(k0 + k) * NP + n0 + n] : 0.f;
        }
        __syncthreads();
#pragma unroll
        for (int k = 0; k < 16; k++) {
            float a[4], b[4];
#pragma unroll
            for (int i = 0; i < 4; i++) a[i] = As[k][ty * 4 + i];
#pragma unroll
            for (int j = 0; j < 4; j++) b[j] = Bs[k][tx * 4 + j];
#pragma unroll
            for (int i = 0; i < 4; i++)
#pragma unroll
                for (int j = 0; j < 4; j++) acc[i][j] += a[i] * b[j];
        }
        __syncthreads();
    }
#pragma unroll
    for (int i = 0; i < 4; i++) {
        float bb = bias[m0 + ty * 4 + i];
#pragma unroll
        for (int j = 0; j < 4; j++) {
            float v = acc[i][j] + bb;
            if (RELU) v = fmaxf(v, 0.f);
            Y[(m0 + ty * 4 + i) * NP + n0 + tx * 4 + j] = v;
        }
    }
}

// ---------------- direct 3x3 conv, pad 1 ----------------
// in: (2, IC, 192, 192), out: (2, OC, 192, 192)
// block = 16x16 spatial tile; each block computes up to 16 output channels.
template<int SRC, int DST, bool RELU>
__global__ void k_conv3x3(const float* __restrict__ W, const float* __restrict__ bias,
                          int IC, int OC) {
    const float* __restrict__ in = buf_ptr(SRC);
    float* __restrict__ out = buf_ptr(DST);

    __shared__ float s_in[16][18][18];
    __shared__ float s_w[16][16][9];
    const int tx = threadIdx.x, ty = threadIdx.y;
    const int tid = ty * 16 + tx;
    const int x0 = blockIdx.x * 16, y0 = blockIdx.y * 16;
    const int noct = (OC + 15) / 16;
    const int b = blockIdx.z / noct;
    const int oc0 = (blockIdx.z % noct) * 16;

    float acc[16];
#pragma unroll
    for (int o = 0; o < 16; o++) acc[o] = 0.f;

    for (int ic0 = 0; ic0 < IC; ic0 += 16) {
        for (int i = tid; i < 16 * 18 * 18; i += 256) {
            int ic = i / 324;
            int r = i - ic * 324;
            int yy = r / 18, xx = r - yy * 18;
            int gy = y0 + yy - 1, gx = x0 + xx - 1;
            float v = 0.f;
            if (gy >= 0 && gy < WOUT && gx >= 0 && gx < WOUT)
                v = in[((b * IC + ic0 + ic) * WOUT + gy) * WOUT + gx];
            s_in[ic][yy][xx] = v;
        }
        for (int i = tid; i < 16 * 16 * 9; i += 256) {
            int o = i / 144;
            int r = i - o * 144;
            int ic = r / 9, j = r - ic * 9;
            float v = 0.f;
            if (oc0 + o < OC) v = W[((oc0 + o) * IC + ic0 + ic) * 9 + j];
            s_w[o][ic][j] = v;
        }
        __syncthreads();
#pragma unroll 4
        for (int ic = 0; ic < 16; ic++) {
            float v[9];
#pragma unroll
            for (int ky = 0; ky < 3; ky++)
#pragma unroll
                for (int kx = 0; kx < 3; kx++)
                    v[ky * 3 + kx] = s_in[ic][ty + ky][tx + kx];
#pragma unroll
            for (int o = 0; o < 16; o++) {
#pragma unroll
                for (int j = 0; j < 9; j++) acc[o] += s_w[o][ic][j] * v[j];
            }
        }
        __syncthreads();
    }
#pragma unroll
    for (int o = 0; o < 16; o++) {
        if (oc0 + o < OC) {
            float v = acc[o] + bias[oc0 + o];
            if (RELU) v = fmaxf(v, 0.f);
            out[((b * OC + oc0 + o) * WOUT + y0 + ty) * WOUT + x0 + tx] = v;
        }
    }
}

// ---------------- gather helper ----------------
__device__ __forceinline__ void gather_h(const float* __restrict__ xbc, int iy, int ix,
                                         float* h) {
#pragma unroll
    for (int dy = 0; dy < 3; dy++)
#pragma unroll
        for (int dx = 0; dx < 3; dx++) {
            int yy = iy + dy - 1, xx = ix + dx - 1;
            h[dy * 3 + dx] =
                (yy >= 0 && yy < HIN && xx >= 0 && xx < HIN) ? xbc[yy * HIN + xx] : 0.f;
        }
}

// ---------------- gather + softmax(dw) mean ----------------
__global__ void k_mean(const float* __restrict__ x, const int* __restrict__ imY,
                       const int* __restrict__ imX) {
    int idx = blockIdx.x * blockDim.x + threadIdx.x;
    if (idx >= 2 * 64 * NP) return;
    int p = idx % NP;
    int c = (idx / NP) & 63;
    int b = idx / (64 * NP);
    int iy = imY[p], ix = imX[p];
    const float* xbc = x + (b * 64 + c) * (HIN * HIN);
    float h[9];
    gather_h(xbc, iy, ix, h);
    float d[9], mx = -1e30f;
#pragma unroll
    for (int k = 0; k < 9; k++) {
        d[k] = g_dw[(c * 9 + k) * NP + p];
        mx = fmaxf(mx, d[k]);
    }
    float s = 0.f, m = 0.f;
#pragma unroll
    for (int k = 0; k < 9; k++) {
        float e = __expf(d[k] - mx);
        s += e;
        m += h[k] * e;
    }
    g_mean[idx] = m / s;
}

// ---------------- bw + softmax + xa ----------------
__global__ void k_xa(const float* __restrict__ x, const int* __restrict__ imY,
                     const int* __restrict__ imX) {
    int idx = blockIdx.x * blockDim.x + threadIdx.x;
    if (idx >= 2 * 64 * NP) return;
    int p = idx % NP;
    int c = (idx / NP) & 63;
    int b = idx / (64 * NP);
    int iy = imY[p], ix = imX[p];
    const float* xbc = x + (b * 64 + c) * (HIN * HIN);
    float h[9];
    gather_h(xbc, iy, ix, h);
    float m = g_mean[idx];
    float sd = g_sigma[(b * 2 + 0) * NP + p];
    float sr = g_sigma[(b * 2 + 1) * NP + p];
    float bw[9], mx = -1e30f;
#pragma unroll
    for (int k = 0; k < 9; k++) {
        float d = g_dw[(c * 9 + k) * NP + p];
        bw[k] = sd * d + sr * fabsf(h[k] - m);
        mx = fmaxf(mx, bw[k]);
    }
    float s = 0.f, acc = 0.f;
#pragma unroll
    for (int k = 0; k < 9; k++) {
        float e = __expf(bw[k] - mx);
        s += e;
        acc += h[k] * e;
    }
    g_xa[idx] = acc / s;
}

// ---------------- per-pixel 64x3 contraction ----------------
__global__ void k_out(float* __restrict__ out) {
    int idx = blockIdx.x * blockDim.x + threadIdx.x;
    if (idx >= 2 * NP) return;
    int p = idx % NP, b = idx / NP;
    float a0 = 0.f, a1 = 0.f, a2 = 0.f;
#pragma unroll 8
    for (int c = 0; c < 64; c++) {
        float v = g_xa[(b * 64 + c) * NP + p];
        a0 += v * g_pw[(c * 3 + 0) * NP + p];
        a1 += v * g_pw[(c * 3 + 1) * NP + p];
        a2 += v * g_pw[(c * 3 + 2) * NP + p];
    }
    out[(b * 3 + 0) * NP + p] = a0;
    out[(b * 3 + 1) * NP + p] = a1;
    out[(b * 3 + 2) * NP + p] = a2;
}

// ---------------- launch ----------------
extern "C" void kernel_launch(void* const* d_in, const int* in_sizes, int n_in,
                              void* d_out, int out_size) {
    const float* x      = (const float*)d_in[0];
    const float* pose   = (const float*)d_in[1];
    const int*   imY    = (const int*)d_in[2];
    const int*   imX    = (const int*)d_in[3];
    const float* sig_w1 = (const float*)d_in[4];
    const float* sig_b1 = (const float*)d_in[5];
    const float* sig_w2 = (const float*)d_in[6];
    const float* sig_b2 = (const float*)d_in[7];
    const float* sig_w3 = (const float*)d_in[8];
    const float* sig_b3 = (const float*)d_in[9];
    const float* dw_w1  = (const float*)d_in[10];
    const float* dw_b1  = (const float*)d_in[11];
    const float* dw_w2  = (const float*)d_in[12];
    const float* dw_b2  = (const float*)d_in[13];
    const float* dw_w3  = (const float*)d_in[14];
    const float* dw_b3  = (const float*)d_in[15];
    const float* pw_w1  = (const float*)d_in[16];
    const float* pw_b1  = (const float*)d_in[17];
    const float* pw_w2  = (const float*)d_in[18];
    const float* pw_b2  = (const float*)d_in[19];
    const float* pw_w3  = (const float*)d_in[20];
    const float* pw_b3  = (const float*)d_in[21];

    const int NT = NP / 64;  // 576 pixel tiles

    // dw chain: 3 -> 64 -> 256 -> 576
    k_gemm1x1<-1, BUF_A, true ><<<dim3(NT, 1), 256>>>(dw_w1, dw_b1, pose, 3);
    k_gemm1x1<BUF_A, BUF_B, true ><<<dim3(NT, 4), 256>>>(dw_w2, dw_b2, nullptr, 64);
    k_gemm1x1<BUF_B, BUF_DW, false><<<dim3(NT, 9), 256>>>(dw_w3, dw_b3, nullptr, 256);
    // pw chain: 3 -> 64 -> 256 -> 192
    k_gemm1x1<-1, BUF_A, true ><<<dim3(NT, 1), 256>>>(pw_w1, pw_b1, pose, 3);
    k_gemm1x1<BUF_A, BUF_B, true ><<<dim3(NT, 4), 256>>>(pw_w2, pw_b2, nullptr, 64);
    k_gemm1x1<BUF_B, BUF_PW, false><<<dim3(NT, 3), 256>>>(pw_w3, pw_b3, nullptr, 256);

    // gather + softmax(dw)-weighted mean
    k_mean<<<(2 * 64 * NP) / 256, 256>>>(x, imY, imX);

    // sigma net: 3x3 convs, pad 1
    k_conv3x3<BUF_MEAN, BUF_S1, true ><<<dim3(12, 12, 2 * 4), dim3(16, 16)>>>(sig_w1, sig_b1, 64, 64);
    k_conv3x3<BUF_S1, BUF_S2, true ><<<dim3(12, 12, 2 * 4), dim3(16, 16)>>>(sig_w2, sig_b2, 64, 64);
    k_conv3x3<BUF_S2, BUF_SIGMA, false><<<dim3(12, 12, 2 * 1), dim3(16, 16)>>>(sig_w3, sig_b3, 64, 2);

    // bw + softmax + xa
    k_xa<<<(2 * 64 * NP) / 256, 256>>>(x, imY, imX);

    // out[b,o,p] = sum_c xa[b,c,p] * pw[c,o,p]
    k_out<<<(2 * NP + 255) / 256, 256>>>((float*)d_out);
}